// round 2
// baseline (speedup 1.0000x reference)
#include <cuda_runtime.h>

// ---------------- device scratch ----------------
__device__ float g_kT[16777216];   // [b][d][n] transposed K
__device__ float g_v [16777216];   // [b][n][d]
__device__ float g_slots[32768];   // [b][k][d]
__device__ float g_q[32768];
__device__ float g_Up[262144];     // [chunk(8)][b][k][d] partial updates
__device__ float g_Sp[4096];       // [chunk(8)][b][k]    partial attn sums
__device__ float g_WqT [4096];     // [d][e]
__device__ float g_wihT[12288];    // [d][j<192]
__device__ float g_whhT[12288];
__device__ float g_w1T [8192];     // [d][j<128]
__device__ float g_w2T [8192];     // [j<128][o<64]

#define FMA2(acc, a, b) asm("fma.rn.f32x2 %0, %1, %2, %0;" : "+l"(acc) : "l"(a), "l"(b))

__device__ __forceinline__ float sigf(float x) { return 1.f / (1.f + __expf(-x)); }

// ---------------- one-shot weight transpose ----------------
__global__ void transpose_weights(const float* __restrict__ Wq, const float* __restrict__ wih,
                                  const float* __restrict__ whh, const float* __restrict__ w1,
                                  const float* __restrict__ w2) {
    int t = blockIdx.x * 256 + threadIdx.x;
    const int T = 32 * 256;
    for (int i = t; i < 4096; i += T)  { int e = i >> 6, d = i & 63;  g_WqT[d*64 + e]  = Wq[i]; }
    for (int i = t; i < 12288; i += T) { int j = i >> 6, d = i & 63;  g_wihT[d*192 + j] = wih[i];
                                                                      g_whhT[d*192 + j] = whh[i]; }
    for (int i = t; i < 8192; i += T)  { int j = i >> 6, d = i & 63;  g_w1T[d*128 + j] = w1[i]; }
    for (int i = t; i < 8192; i += T)  { int o = i >> 7, j = i & 127; g_w2T[j*64 + o]  = w2[i]; }
}

// ---------------- slots init ----------------
__global__ void init_slots(const float* __restrict__ noise, const float* __restrict__ mu,
                           const float* __restrict__ lsig) {
    int i = blockIdx.x * 256 + threadIdx.x;   // grid 128
    int d = i & 63;
    g_slots[i] = __ldg(mu + d) + __expf(__ldg(lsig + d)) * noise[i];
}

// ---------------- fused input LN + K^T/V projection ----------------
__global__ void __launch_bounds__(256) ln_kv(const float* __restrict__ inp,
        const float* __restrict__ Wk, const float* __restrict__ Wv,
        const float* __restrict__ lng, const float* __restrict__ lnb) {
    __shared__ __align__(16) float xs[32 * 66];
    __shared__ __align__(16) float ws[128 * 64];  // Wk rows 0..63, Wv rows 64..127; reused as staging
    int t = threadIdx.x;
    int r0 = blockIdx.x * 32;
    const float* ip = inp + (size_t)r0 * 64;
    #pragma unroll
    for (int i = 0; i < 8; i++) { int id = t + 256*i; xs[(id>>6)*66 + (id&63)] = ip[id]; }
    #pragma unroll
    for (int i = 0; i < 16; i++) { int id = t + 256*i; ws[id] = Wk[id]; ws[4096+id] = Wv[id]; }
    __syncthreads();
    {   // LayerNorm: 8 threads/row
        int row = t >> 3, sub = t & 7;
        float s = 0.f, ss = 0.f;
        #pragma unroll
        for (int i = 0; i < 8; i++) { float x = xs[row*66 + sub*8 + i]; s += x; ss += x*x; }
        s += __shfl_xor_sync(~0u, s, 1); ss += __shfl_xor_sync(~0u, ss, 1);
        s += __shfl_xor_sync(~0u, s, 2); ss += __shfl_xor_sync(~0u, ss, 2);
        s += __shfl_xor_sync(~0u, s, 4); ss += __shfl_xor_sync(~0u, ss, 4);
        float mu = s * 0.015625f;
        float rstd = rsqrtf(ss * 0.015625f - mu*mu + 1e-5f);
        #pragma unroll
        for (int i = 0; i < 8; i++) {
            int f = sub*8 + i;
            xs[row*66 + f] = (xs[row*66 + f] - mu) * rstd * __ldg(lng+f) + __ldg(lnb+f);
        }
    }
    __syncthreads();
    // GEMM: thread (tx,ty): rows tx,tx+16; out dims ty*8..ty*8+7 (K if ty<8 else V)
    int tx = t & 15, ty = t >> 4;
    unsigned long long acc[8][2];
    #pragma unroll
    for (int j = 0; j < 8; j++) { acc[j][0] = 0ull; acc[j][1] = 0ull; }
    const unsigned long long* ws2 = (const unsigned long long*)ws;
    #pragma unroll 8
    for (int f2 = 0; f2 < 32; f2++) {
        unsigned long long a0 = *(const unsigned long long*)&xs[tx*66 + 2*f2];
        unsigned long long a1 = *(const unsigned long long*)&xs[(tx+16)*66 + 2*f2];
        #pragma unroll
        for (int j = 0; j < 8; j++) {
            unsigned long long bb = ws2[(ty*8 + j)*32 + f2];
            FMA2(acc[j][0], bb, a0);
            FMA2(acc[j][1], bb, a1);
        }
    }
    float cs[8][2];
    #pragma unroll
    for (int j = 0; j < 8; j++)
        #pragma unroll
        for (int i = 0; i < 2; i++) { float2 f = *reinterpret_cast<float2*>(&acc[j][i]); cs[j][i] = f.x + f.y; }

    int b = r0 >> 12, nn0 = r0 & 4095;
    float* os = ws;
    __syncthreads();
    if (ty < 8) {   // K wave -> transposed store
        #pragma unroll
        for (int j = 0; j < 8; j++) {
            int od = ty*8 + j;
            os[tx*66 + od] = cs[j][0];
            os[(tx+16)*66 + od] = cs[j][1];
        }
    }
    __syncthreads();
    #pragma unroll
    for (int i = 0; i < 8; i++) {
        int id = t + 256*i; int d = id >> 5, row = id & 31;
        g_kT[((size_t)b*64 + d)*4096 + nn0 + row] = os[row*66 + d];
    }
    __syncthreads();
    if (ty >= 8) {  // V wave -> natural store
        #pragma unroll
        for (int j = 0; j < 8; j++) {
            int od = ty*8 + j - 64;
            os[tx*66 + od] = cs[j][0];
            os[(tx+16)*66 + od] = cs[j][1];
        }
    }
    __syncthreads();
    #pragma unroll
    for (int i = 0; i < 8; i++) {
        int id = t + 256*i; int d = id & 63, row = id >> 6;
        g_v[((size_t)r0 + row)*64 + d] = os[row*66 + d];
    }
}

// ---------------- slots LN + Q projection ----------------
__global__ void __launch_bounds__(256) q_kernel(const float* __restrict__ lng,
                                                const float* __restrict__ lnb) {
    __shared__ float sn_s[512];
    int b = blockIdx.x, t = threadIdx.x;
    int w = t >> 5, lane = t & 31;
    float s0 = g_slots[b*512 + w*64 + lane];
    float s1 = g_slots[b*512 + w*64 + 32 + lane];
    float s = s0 + s1, ss = s0*s0 + s1*s1;
    #pragma unroll
    for (int o = 16; o > 0; o >>= 1) { s += __shfl_xor_sync(~0u, s, o); ss += __shfl_xor_sync(~0u, ss, o); }
    float mu = s * 0.015625f;
    float rstd = rsqrtf(ss * 0.015625f - mu*mu + 1e-5f);
    sn_s[w*64 + lane]      = (s0 - mu)*rstd*__ldg(lng+lane)    + __ldg(lnb+lane);
    sn_s[w*64 + 32 + lane] = (s1 - mu)*rstd*__ldg(lng+32+lane) + __ldg(lnb+32+lane);
    __syncthreads();
    int e = t & 63, k2 = t >> 6;
    #pragma unroll
    for (int kk = k2; kk < 8; kk += 4) {
        float a = 0.f;
        #pragma unroll 16
        for (int d = 0; d < 64; d++) a += sn_s[kk*64 + d] * __ldg(&g_WqT[d*64 + e]);
        g_q[b*512 + kk*64 + e] = a;
    }
}

// ---------------- attention: logits+softmax+eps, partial U/S per chunk ----------------
__global__ void __launch_bounds__(256) attn_kernel() {
    __shared__ float qs[512];
    __shared__ float attn_s[512 * 9];
    __shared__ float red[4 * 512];
    __shared__ float sred[64];
    int t = threadIdx.x, b = blockIdx.y, n0 = blockIdx.x * 512;
    qs[t] = g_q[b*512 + t]; qs[t+256] = g_q[b*512 + 256 + t];
    __syncthreads();

    float sacc[8];
    #pragma unroll
    for (int j = 0; j < 8; j++) sacc[j] = 0.f;
    #pragma unroll
    for (int rep = 0; rep < 2; rep++) {
        int nl = rep*256 + t;
        const float* kp = g_kT + (size_t)b*262144 + n0 + nl;
        float l[8];
        #pragma unroll
        for (int j = 0; j < 8; j++) l[j] = 0.f;
        #pragma unroll 16
        for (int d = 0; d < 64; d++) {
            float kd = __ldg(kp + d*4096);
            #pragma unroll
            for (int j = 0; j < 8; j++) l[j] += kd * qs[j*64 + d];
        }
        float m = l[0];
        #pragma unroll
        for (int j = 1; j < 8; j++) m = fmaxf(m, l[j]);
        float s = 0.f, e[8];
        #pragma unroll
        for (int j = 0; j < 8; j++) { e[j] = __expf((l[j] - m) * 0.125f); s += e[j]; }
        float inv = 1.0f / s;
        #pragma unroll
        for (int j = 0; j < 8; j++) {
            float a = e[j]*inv + 1e-8f;
            sacc[j] += a;
            attn_s[nl*9 + j] = a;
        }
    }
    // deterministic S reduce: warp shfl, then fixed-order cross-warp sum
    #pragma unroll
    for (int j = 0; j < 8; j++) {
        float v = sacc[j];
        #pragma unroll
        for (int o = 16; o > 0; o >>= 1) v += __shfl_xor_sync(~0u, v, o);
        if ((t & 31) == 0) sred[(t>>5)*8 + j] = v;
    }
    __syncthreads();
    if (t < 8) {
        float v = 0.f;
        #pragma unroll
        for (int w = 0; w < 8; w++) v += sred[w*8 + t];
        g_Sp[blockIdx.x*512 + b*8 + t] = v;
    }
    // update phase: thread (d, grp) sums 128 tokens for all 8 slots
    int d = t & 63, grp = t >> 6;
    float acc[8];
    #pragma unroll
    for (int j = 0; j < 8; j++) acc[j] = 0.f;
    const float* vp = g_v + ((size_t)b*4096 + n0)*64 + d;
    int nb = grp * 128;
    #pragma unroll 4
    for (int n = nb; n < nb + 128; n++) {
        float vv = __ldg(vp + n*64);
        #pragma unroll
        for (int j = 0; j < 8; j++) acc[j] += attn_s[n*9 + j] * vv;
    }
    #pragma unroll
    for (int j = 0; j < 8; j++) red[grp*512 + j*64 + d] = acc[j];
    __syncthreads();
    #pragma unroll
    for (int rep = 0; rep < 2; rep++) {
        int e = rep*256 + t;
        float v = red[e] + red[512 + e] + red[1024 + e] + red[1536 + e];
        g_Up[(blockIdx.x*64 + b)*512 + e] = v;
    }
}

// ---------------- GRU + LN + MLP + residual ----------------
__global__ void __launch_bounds__(192) gru_mlp(const float* __restrict__ bih, const float* __restrict__ bhh,
        const float* __restrict__ b1, const float* __restrict__ b2,
        const float* __restrict__ lng, const float* __restrict__ lnb,
        float* __restrict__ out, int last) {
    __shared__ float u_s[64], h_s[64], gi_s[192], gh_s[192], hn_s[64], ln_s[64], h1_s[128];
    int row = blockIdx.x, t = threadIdx.x;
    if (t < 64) {
        float S = 0.f, U = 0.f;
        #pragma unroll
        for (int c = 0; c < 8; c++) { S += g_Sp[c*512 + row]; U += g_Up[c*32768 + row*64 + t]; }
        u_s[t] = U / S;
        h_s[t] = g_slots[row*64 + t];
    }
    __syncthreads();
    {
        float gi = __ldg(bih + t), gh = __ldg(bhh + t);
        #pragma unroll 8
        for (int d = 0; d < 64; d++) {
            gi += u_s[d] * __ldg(&g_wihT[d*192 + t]);
            gh += h_s[d] * __ldg(&g_whhT[d*192 + t]);
        }
        gi_s[t] = gi; gh_s[t] = gh;
    }
    __syncthreads();
    if (t < 64) {
        float r = sigf(gi_s[t] + gh_s[t]);
        float z = sigf(gi_s[64+t] + gh_s[64+t]);
        float n = tanhf(gi_s[128+t] + r * gh_s[128+t]);
        hn_s[t] = (1.f - z)*n + z*h_s[t];
    }
    __syncthreads();
    if (t < 64) {
        float s = 0.f, ss = 0.f;
        #pragma unroll 8
        for (int d = 0; d < 64; d++) { float x = hn_s[d]; s += x; ss += x*x; }
        float mu = s * 0.015625f;
        float rstd = rsqrtf(ss * 0.015625f - mu*mu + 1e-5f);
        ln_s[t] = (hn_s[t] - mu)*rstd*__ldg(lng+t) + __ldg(lnb+t);
    }
    __syncthreads();
    if (t < 128) {
        float h1 = __ldg(b1 + t);
        #pragma unroll 8
        for (int d = 0; d < 64; d++) h1 += ln_s[d] * __ldg(&g_w1T[d*128 + t]);
        h1_s[t] = fmaxf(h1, 0.f);
    }
    __syncthreads();
    if (t < 64) {
        float o = __ldg(b2 + t);
        #pragma unroll 8
        for (int j = 0; j < 128; j++) o += h1_s[j] * __ldg(&g_w2T[j*64 + t]);
        float res = hn_s[t] + o;
        g_slots[row*64 + t] = res;
        if (last) out[row*64 + t] = res;
    }
}

extern "C" void kernel_launch(void* const* d_in, const int* in_sizes, int n_in,
                              void* d_out, int out_size) {
    const float* inputs = (const float*)d_in[0];
    const float* noise  = (const float*)d_in[1];
    const float* mu     = (const float*)d_in[2];
    const float* lsig   = (const float*)d_in[3];
    const float* Wq     = (const float*)d_in[4];
    const float* Wk     = (const float*)d_in[5];
    const float* Wv     = (const float*)d_in[6];
    const float* wih    = (const float*)d_in[7];
    const float* whh    = (const float*)d_in[8];
    const float* bih    = (const float*)d_in[9];
    const float* bhh    = (const float*)d_in[10];
    const float* w1     = (const float*)d_in[11];
    const float* b1     = (const float*)d_in[12];
    const float* w2     = (const float*)d_in[13];
    const float* b2     = (const float*)d_in[14];
    const float* ln_in_g   = (const float*)d_in[15];
    const float* ln_in_b   = (const float*)d_in[16];
    const float* ln_sl_g   = (const float*)d_in[17];
    const float* ln_sl_b   = (const float*)d_in[18];
    const float* ln_mlp_g  = (const float*)d_in[19];
    const float* ln_mlp_b  = (const float*)d_in[20];
    float* out = (float*)d_out;

    transpose_weights<<<32, 256>>>(Wq, wih, whh, w1, w2);
    init_slots<<<128, 256>>>(noise, mu, lsig);
    ln_kv<<<8192, 256>>>(inputs, Wk, Wv, ln_in_g, ln_in_b);
    for (int it = 0; it < 3; it++) {
        q_kernel<<<64, 256>>>(ln_sl_g, ln_sl_b);
        attn_kernel<<<dim3(8, 64), 256>>>();
        gru_mlp<<<512, 192>>>(bih, bhh, b1, b2, ln_mlp_g, ln_mlp_b, out, it == 2);
    }
}